// round 13
// baseline (speedup 1.0000x reference)
#include <cuda_runtime.h>
#include <stdint.h>

#define NPRED    25200
#define PRED_C   9
#define TOPK     1000
#define CONF_T   0.7f
#define IOU_T    0.45f
#define MASKW    32
#define BMAX     32

#define NSLICE   25
#define ROWS_SL  1008
#define FILT_T   256

#define CANDCAP  4096
#define SEL_N    1024
#define FUSE_T   1024

#define NWARPS_F 32
#define TASKS    16872         // sum_w min(1000, 32w+32)

typedef unsigned long long u64;
typedef unsigned int u32;

// ---------------- global scratch ----------------
__device__ int    g_cnt [BMAX * NSLICE];
__device__ u64    g_cand[BMAX * NSLICE * ROWS_SL];

// ---------------- smem layout offsets (bytes) ----------------
#define OFF_SKEY   0                       // u64[4096]  = 32768
#define OFF_SKEY2  32768                   // u64[1024]  = 8192
#define OFF_SKEY3  40960                   // u64[1024]  = 8192
#define OFF_HIST   49152                   // u32[1024]  = 4096
#define OFF_WSUM   53248                   // u32[32]
#define OFF_WOFF   53376                   // u32[32]
#define OFF_SPFX   53504                   // int[33]
#define OFF_MISC   53648                   // int[4]
// B region overlaps SKEY after sort:
#define OFF_SBOX   0                       // float4[1000] = 16000
#define OFF_SAREA  16000                   // float[1000]  = 4000
#define OFF_SSCORE 20000                   // float[1024]  = 4096
#define OFF_SIDX   24096                   // int[1000]    = 4000
// mask region:
#define OFF_SMASK  53664                   // u32[32000] = 128000
#define OFF_SDIAG  181664                  // u32[1024]
#define OFF_SSUP   185760                  // u32[1024]
#define OFF_SVALID 189856                  // u32[32]
#define OFF_SKEEP  189984                  // u32[32]
#define OFF_SREMV  190112                  // u32[32]
#define SMEM_FUSE  190240

// ============================================================
// 1) filter: full-chip pass over predictions
// ============================================================
__global__ __launch_bounds__(FILT_T)
void k_filter(const float* __restrict__ pred)
{
    __shared__ u64 buf[ROWS_SL];
    __shared__ int cnt;

    const int img   = blockIdx.x;
    const int slice = blockIdx.y;
    const int tid   = threadIdx.x;
    const float* p  = pred + (size_t)img * NPRED * PRED_C;

    if (tid == 0) cnt = 0;
    __syncthreads();

    const int base = slice * ROWS_SL;
    #pragma unroll
    for (int r = 0; r < 4; r++) {
        int row = tid + r * FILT_T;
        if (row < ROWS_SL) {
            int i = base + row;
            float obj = p[i * PRED_C + 4];
            float cls = p[i * PRED_C + 5];
            float conf = __fmul_rn(obj, cls);
            if (obj > CONF_T && conf > CONF_T) {
                int pos = atomicAdd(&cnt, 1);
                buf[pos] = ((u64)__float_as_uint(conf) << 32) |
                           (u64)(0xFFFFFFFFu - (u32)i);
            }
        }
    }
    __syncthreads();

    int n = cnt;
    if (tid == 0) g_cnt[img * NSLICE + slice] = n;
    u64* dst = g_cand + (size_t)(img * NSLICE + slice) * ROWS_SL;
    for (int k = tid; k < n; k += FILT_T) dst[k] = buf[k];
}

// ============================================================
// 2) fused: sort + mask + sweep + output, all smem-resident
// ============================================================
#define STEP(b, d) { u32 s = (u32)((int)(alive << (31 - (b))) >> 31); \
                     alive &= ~((d) & s); }

__global__ __launch_bounds__(FUSE_T, 1)
void k_fused(const float* __restrict__ pred,
             float* __restrict__ out,
             float* __restrict__ keep_out)
{
    extern __shared__ unsigned char sraw[];
    u64* skey  = (u64*)(sraw + OFF_SKEY);
    u64* skey2 = (u64*)(sraw + OFF_SKEY2);
    u64* skey3 = (u64*)(sraw + OFF_SKEY3);
    u32* hist  = (u32*)(sraw + OFF_HIST);
    u32* wsum  = (u32*)(sraw + OFF_WSUM);
    u32* woff  = (u32*)(sraw + OFF_WOFF);
    int* spfx  = (int*)(sraw + OFF_SPFX);
    int* misc  = (int*)(sraw + OFF_MISC);
    float4* sbox  = (float4*)(sraw + OFF_SBOX);
    float* sarea  = (float*)(sraw + OFF_SAREA);
    float* sscore = (float*)(sraw + OFF_SSCORE);
    int*   sidx   = (int*)(sraw + OFF_SIDX);
    u32* smask  = (u32*)(sraw + OFF_SMASK);
    u32* sdiag  = (u32*)(sraw + OFF_SDIAG);
    u32* ssup   = (u32*)(sraw + OFF_SSUP);
    u32* svalid = (u32*)(sraw + OFF_SVALID);
    u32* skeep  = (u32*)(sraw + OFF_SKEEP);
    u32* sremv  = (u32*)(sraw + OFF_SREMV);

    const int img = blockIdx.x;
    const int tid = threadIdx.x;
    const int lane = tid & 31, warp = tid >> 5;
    const float* p = pred + (size_t)img * NPRED * PRED_C;

    // ---- zero mask region (overlaps later gather's global loads) ----
    for (int t = tid; t < TOPK * MASKW; t += FUSE_T) smask[t] = 0;
    for (int t = tid; t < 1024; t += FUSE_T) { sdiag[t] = 0; ssup[t] = 0; }

    // ---- prefix over slice counts (warp 0) ----
    if (tid < 32) {
        int c = (tid < NSLICE) ? g_cnt[img * NSLICE + tid] : 0;
        int x = c;
        #pragma unroll
        for (int d = 1; d < 32; d <<= 1) {
            int y = __shfl_up_sync(0xFFFFFFFFu, x, d);
            if ((tid & 31) >= d) x += y;
        }
        spfx[tid + 1] = x;
        if (tid == 0) spfx[0] = 0;
        if (tid == 31) misc[0] = x;
    }
    __syncthreads();

    int total = misc[0];
    if (total > CANDCAP) total = CANDCAP;

    // ---- parallel gather via binary search ----
    for (int k = tid; k < total; k += FUSE_T) {
        int lo = 0, hi = NSLICE;
        #pragma unroll
        for (int it = 0; it < 5; it++) {
            int mid = (lo + hi) >> 1;
            if (spfx[mid] <= k) lo = mid; else hi = mid;
        }
        skey[k] = g_cand[(size_t)(img * NSLICE + lo) * ROWS_SL + (k - spfx[lo])];
    }
    for (int k = total + tid; k < CANDCAP; k += FUSE_T) skey[k] = 0ull;
    hist[tid] = 0;
    __syncthreads();

    // ---- histogram of conf bits ----
    for (int k = tid; k < total; k += FUSE_T) {
        u32 bits = (u32)(skey[k] >> 32);
        int b = (int)((bits - 0x3F000000u) >> 13);
        b = b < 0 ? 0 : (b > 1023 ? 1023 : b);
        atomicAdd(&hist[b], 1u);
    }
    __syncthreads();

    // ---- hierarchical suffix sums ----
    {
        u32 x = hist[tid];
        #pragma unroll
        for (int d = 1; d < 32; d <<= 1) {
            u32 y = __shfl_down_sync(0xFFFFFFFFu, x, d);
            if (lane + d < 32) x += y;
        }
        if (lane == 0) wsum[warp] = x;
        __syncthreads();
        if (warp == 0) {
            u32 t = wsum[lane];
            u32 sx = t;
            #pragma unroll
            for (int d = 1; d < 32; d <<= 1) {
                u32 y = __shfl_down_sync(0xFFFFFFFFu, sx, d);
                if (lane + d < 32) sx += y;
            }
            woff[lane] = sx - t;
        }
        __syncthreads();
        hist[tid] = x + woff[warp];
        __syncthreads();
    }

    int need = total < TOPK ? total : TOPK;
    if ((int)hist[tid] >= need && (tid == 1023 || (int)hist[tid + 1] < need))
        misc[1] = tid;
    if (tid == 0) misc[2] = 0;
    __syncthreads();

    int T = misc[1];
    int kept = (int)hist[T];
    bool fallback = (kept > SEL_N);

    u64 mykey;
    if (!fallback) {
        for (int k = tid; k < CANDCAP; k += FUSE_T) {
            bool take = false;
            u64 key = 0ull;
            if (k < total) {
                key = skey[k];
                u32 bits = (u32)(key >> 32);
                int b = (int)((bits - 0x3F000000u) >> 13);
                b = b < 0 ? 0 : (b > 1023 ? 1023 : b);
                take = (b >= T);
            }
            u32 bal = __ballot_sync(0xFFFFFFFFu, take);
            if (bal) {
                int nset = __popc(bal);
                int base_pos;
                if (lane == __ffs(bal) - 1)
                    base_pos = atomicAdd(&misc[2], nset);
                base_pos = __shfl_sync(0xFFFFFFFFu, base_pos, __ffs(bal) - 1);
                if (take) {
                    int off = __popc(bal & ((1u << lane) - 1u));
                    skey2[base_pos + off] = key;
                }
            }
        }
        __syncthreads();
        for (int k = kept + tid; k < SEL_N; k += FUSE_T) skey2[k] = 0ull;
        __syncthreads();

        // double-buffered hybrid bitonic, 1 elem/thread
        u64 v = skey2[tid];
        #pragma unroll
        for (int k = 2; k <= 32; k <<= 1) {
            #pragma unroll
            for (int j = k >> 1; j > 0; j >>= 1) {
                u64 o = __shfl_xor_sync(0xFFFFFFFFu, v, j);
                bool keep_max = ((tid & j) == 0) == ((tid & k) == 0);
                bool vbig = v > o;
                v = (keep_max == vbig) ? v : o;
            }
        }
        u64* bufs[2] = { skey2, skey3 };
        int cur = 0;
        bufs[cur][tid] = v;
        __syncthreads();
        #pragma unroll
        for (int k = 64; k <= SEL_N; k <<= 1) {
            for (int j = k >> 1; j >= 32; j >>= 1) {
                u64 o = bufs[cur][tid ^ j];
                bool keep_max = ((tid & j) == 0) == ((tid & k) == 0);
                bool vbig = v > o;
                v = (keep_max == vbig) ? v : o;
                bufs[cur ^ 1][tid] = v;
                cur ^= 1;
                __syncthreads();
            }
            #pragma unroll
            for (int j = 16; j > 0; j >>= 1) {
                u64 o = __shfl_xor_sync(0xFFFFFFFFu, v, j);
                bool keep_max = ((tid & j) == 0) == ((tid & k) == 0);
                bool vbig = v > o;
                v = (keep_max == vbig) ? v : o;
            }
            if (k < SEL_N) {
                bufs[cur][tid] = v;
                __syncthreads();
            }
        }
        mykey = v;
    } else {
        u64* sbuf = skey;
        const int n = CANDCAP;
        __syncthreads();
        for (int k = 2; k <= n; k <<= 1) {
            for (int j = k >> 1; j > 0; j >>= 1) {
                for (int q = 0; q < n; q += FUSE_T) {
                    int i = tid + q;
                    int ixj = i ^ j;
                    if (ixj > i) {
                        u64 a = sbuf[i], b = sbuf[ixj];
                        if (((i & k) == 0) ? (a < b) : (a > b)) {
                            sbuf[i] = b; sbuf[ixj] = a;
                        }
                    }
                }
                __syncthreads();
            }
        }
        mykey = sbuf[tid];
    }
    __syncthreads();   // all A-region reads done before B-region writes

    // ---- extraction into smem B region ----
    {
        u64 key = mykey;
        if (tid < TOPK) {
            float4 b; float sc, ar; int idx;
            if ((key >> 32) != 0ull) {
                idx = (int)(0xFFFFFFFFu - (u32)(key & 0xFFFFFFFFull));
                sc  = __uint_as_float((u32)(key >> 32));
                float x = p[idx * PRED_C + 0];
                float y = p[idx * PRED_C + 1];
                float w = p[idx * PRED_C + 2];
                float h = p[idx * PRED_C + 3];
                float hw = __fmul_rn(w, 0.5f);
                float hh = __fmul_rn(h, 0.5f);
                b = make_float4(__fsub_rn(x, hw), __fsub_rn(y, hh),
                                __fadd_rn(x, hw), __fadd_rn(y, hh));
                ar = __fmul_rn(__fsub_rn(b.z, b.x), __fsub_rn(b.w, b.y));
            } else {
                idx = -1; sc = -1.0f; ar = 0.0f;
                b = make_float4(0.f, 0.f, 0.f, 0.f);
            }
            sbox[tid] = b;
            sarea[tid] = ar;
            sscore[tid] = sc;
            sidx[tid] = idx;
        } else {
            sscore[tid] = -1.0f;
        }
    }
    __syncthreads();

    // ---- mask phase: 32 warps, balanced upper-triangle tasks ----
    {
        const int gw = warp;
        int u    = (int)(((long long)gw * TASKS) / NWARPS_F);
        int uend = (int)(((long long)(gw + 1) * TASKS) / NWARPS_F);

        int w = 0, acc = 0;
        while (true) {
            int cw = 32 * w + 32; if (cw > TOPK) cw = TOPK;
            if (acc + cw > u) break;
            acc += cw; w++;
        }
        int i  = u - acc;
        int cw = 32 * w + 32; if (cw > TOPK) cw = TOPK;

        int j = w * 32 + lane;
        bool jv = (j < TOPK);
        float4 bj = sbox[jv ? j : 0];
        float  aj = sarea[jv ? j : 0];

        for (; u < uend; ++u) {
            if (i == cw) {
                w++; i = 0;
                cw = 32 * w + 32; if (cw > TOPK) cw = TOPK;
                j = w * 32 + lane;
                jv = (j < TOPK);
                bj = sbox[jv ? j : 0];
                aj = sarea[jv ? j : 0];
            }
            float4 bi = sbox[i];
            float  ai = sarea[i];
            float lx = fmaxf(bi.x, bj.x);
            float ly = fmaxf(bi.y, bj.y);
            float rx = fminf(bi.z, bj.z);
            float ry = fminf(bi.w, bj.w);
            float iw = fmaxf(__fsub_rn(rx, lx), 0.0f);
            float ih = fmaxf(__fsub_rn(ry, ly), 0.0f);
            float inter = __fmul_rn(iw, ih);
            bool sup = false;
            if (j > i && jv && inter > 0.0f) {
                float denom = __fadd_rn(__fsub_rn(__fadd_rn(ai, aj), inter), 1e-7f);
                sup = (__fdiv_rn(inter, denom) > IOU_T);
            }
            u32 word = __ballot_sync(0xFFFFFFFFu, sup);
            if (lane == 0) {
                smask[i * MASKW + w] = word;
                int c = i >> 5;
                if (w == c)          sdiag[i] = word;
                else if (w == c + 1) ssup[i]  = word;
            }
            i++;
        }
    }

    // validity ballots + sremv init
    {
        float sc = sscore[tid];
        u32 vb = __ballot_sync(0xFFFFFFFFu, sc > CONF_T);
        if (lane == 0) svalid[warp] = vb;
        if (tid < 32) sremv[tid] = 0;
    }
    __syncthreads();

    // ---- sweep: pipelined resolve (warp 0) / accumulate (warps 1-31) ----
    u32 carry = 0;
    for (int w = 0; w < 32; w++) {
        if (warp == 0) {
            const uint4* dq = (const uint4*)(sdiag + w * 32);
            uint4 q0 = dq[0], q1 = dq[1], q2 = dq[2], q3 = dq[3];
            uint4 q4 = dq[4], q5 = dq[5], q6 = dq[6], q7 = dq[7];
            u32 alive = svalid[w] & ~(sremv[w] | carry);
            STEP( 0, q0.x) STEP( 1, q0.y) STEP( 2, q0.z) STEP( 3, q0.w)
            STEP( 4, q1.x) STEP( 5, q1.y) STEP( 6, q1.z) STEP( 7, q1.w)
            STEP( 8, q2.x) STEP( 9, q2.y) STEP(10, q2.z) STEP(11, q2.w)
            STEP(12, q3.x) STEP(13, q3.y) STEP(14, q3.z) STEP(15, q3.w)
            STEP(16, q4.x) STEP(17, q4.y) STEP(18, q4.z) STEP(19, q4.w)
            STEP(20, q5.x) STEP(21, q5.y) STEP(22, q5.z) STEP(23, q5.w)
            STEP(24, q6.x) STEP(25, q6.y) STEP(26, q6.z) STEP(27, q6.w)
            STEP(28, q7.x) STEP(29, q7.y) STEP(30, q7.z) STEP(31, q7.w)
            if (lane == 0) skeep[w] = alive;
            u32 contrib = ssup[w * 32 + lane] & (0u - ((alive >> lane) & 1u));
            carry = __reduce_or_sync(0xFFFFFFFFu, contrib);
        } else if (w > 0) {
            // accumulate chunk w-1's kept rows (each warp owns ~1 bit)
            u32 a = skeep[w - 1];
            int b = warp - 1;
            u32 partial = 0;
            if ((a >> b) & 1u) {
                int row = (w - 1) * 32 + b;
                if (row < TOPK) partial = smask[row * 32 + lane];
            }
            if (b + 31 < 32) {  // warp 1 also covers bit 31... (only b=0 gets 2nd)
                if ((a >> (b + 31)) & 1u) {
                    int row = (w - 1) * 32 + b + 31;
                    if (row < TOPK) partial |= smask[row * 32 + lane];
                }
            }
            if (partial) atomicOr(&sremv[lane], partial);
        }
        __syncthreads();
    }

    // ---- outputs ----
    if (tid < TOPK) {
        bool kp = (skeep[tid >> 5] >> (tid & 31)) & 1u;
        float o0=0.f,o1=0.f,o2=0.f,o3=0.f,o4=0.f,o6=0.f,o7=0.f,o8=0.f;
        if (kp) {
            float4 b = sbox[tid];
            o0 = b.x; o1 = b.y; o2 = b.z; o3 = b.w;
            o4 = sscore[tid];
            int idx = sidx[tid];
            o6 = p[idx * PRED_C + 6];
            o7 = p[idx * PRED_C + 7];
            o8 = p[idx * PRED_C + 8];
        }
        float* orow = out + ((size_t)img * TOPK + tid) * PRED_C;
        orow[0]=o0; orow[1]=o1; orow[2]=o2; orow[3]=o3;
        orow[4]=o4; orow[5]=0.0f;
        orow[6]=o6; orow[7]=o7; orow[8]=o8;
        keep_out[(size_t)img * TOPK + tid] = kp ? 1.0f : 0.0f;
    }
}

extern "C" void kernel_launch(void* const* d_in, const int* in_sizes, int n_in,
                              void* d_out, int out_size)
{
    const float* pred = (const float*)d_in[0];
    int B = in_sizes[0] / (NPRED * PRED_C);

    float* out  = (float*)d_out;
    float* keep = out + (size_t)B * TOPK * PRED_C;

    static bool attr_set = false;
    if (!attr_set) {
        cudaFuncSetAttribute(k_fused, cudaFuncAttributeMaxDynamicSharedMemorySize,
                             SMEM_FUSE);
        attr_set = true;
    }

    k_filter<<<dim3(B, NSLICE), FILT_T>>>(pred);
    k_fused<<<B, FUSE_T, SMEM_FUSE>>>(pred, out, keep);
}

// round 14
// speedup vs baseline: 1.8218x; 1.8218x over previous
#include <cuda_runtime.h>
#include <stdint.h>

#define NPRED    25200
#define PRED_C   9
#define TOPK     1000
#define CONF_T   0.7f
#define IOU_T    0.45f
#define MASKW    32
#define BMAX     32

#define NSLICE   25
#define ROWS_SL  1008
#define FS_T     1024

#define CANDCAP  4096
#define SEL_N    1024

#define MSLICES  16
#define MASK_T   256
#define NWARPS_M (MSLICES * (MASK_T / 32))    // 128 warps per image
#define TASKS    16872                        // sum_w min(1000, 32w+32)

#define SWEEP_T  512

typedef unsigned long long u64;
typedef unsigned int u32;

// ---------------- global scratch ----------------
__device__ int    g_done[BMAX];                 // zero-init; reset in-graph
__device__ int    g_cnt1[BMAX];                 // zero-init; reset in-graph
__device__ u64    g_cand1[BMAX * CANDCAP];
__device__ float4 g_box [BMAX * 1024];
__device__ float  g_score[BMAX * 1024];
__device__ float  g_area[BMAX * 1024];
__device__ int    g_idx [BMAX * 1024];
__device__ u32    g_mask[BMAX * TOPK * MASKW];  // lower-tri words never written (stay 0)

// ============================================================
// 1) filtersort: wide filter phase; last CTA per image sorts
// ============================================================
__global__ __launch_bounds__(FS_T, 1)
void k_filtersort(const float* __restrict__ pred)
{
    extern __shared__ unsigned char sraw[];
    u64* skey  = (u64*)sraw;                    // CANDCAP
    u64* skey2 = skey + CANDCAP;                // SEL_N (buffer A)
    u64* skey3 = skey2 + SEL_N;                 // SEL_N (buffer B)
    u32* hist  = (u32*)(skey3 + SEL_N);         // 1024
    u32* wsum  = hist + 1024;                   // 32
    u32* woff  = wsum + 32;                     // 32
    int* misc  = (int*)(woff + 32);             // [0]=total [1]=T [2]=kept [3]=flag

    const int img = blockIdx.x;
    const int tid = threadIdx.x;
    const int lane = tid & 31, warp = tid >> 5;
    const float* p = pred + (size_t)img * NPRED * PRED_C;

    // ---- filter phase: my 1008-row slice, warp-aggregated global push ----
    {
        int i = blockIdx.y * ROWS_SL + tid;
        bool take = false;
        u64 key = 0ull;
        if (tid < ROWS_SL) {
            float obj = p[i * PRED_C + 4];
            float cls = p[i * PRED_C + 5];
            float conf = __fmul_rn(obj, cls);
            take = (obj > CONF_T) && (conf > CONF_T);
            key = ((u64)__float_as_uint(conf) << 32) |
                  (u64)(0xFFFFFFFFu - (u32)i);
        }
        u32 bal = __ballot_sync(0xFFFFFFFFu, take);
        if (bal) {
            int nset = __popc(bal);
            int leader = __ffs(bal) - 1;
            int base_pos;
            if (lane == leader) base_pos = atomicAdd(&g_cnt1[img], nset);
            base_pos = __shfl_sync(0xFFFFFFFFu, base_pos, leader);
            if (take) {
                int pos = base_pos + __popc(bal & ((1u << lane) - 1u));
                if (pos < CANDCAP) g_cand1[img * CANDCAP + pos] = key;
            }
        }
    }
    __threadfence();                 // make my pushes visible before arrival
    __syncthreads();
    if (tid == 0) {
        int old = atomicAdd(&g_done[img], 1);
        misc[3] = (old == (int)gridDim.y - 1);
    }
    __syncthreads();
    if (!misc[3]) return;            // non-closer CTAs exit
    __threadfence();                 // acquire: see all images' pushes

    if (tid == 0) {
        misc[0] = atomicAdd(&g_cnt1[img], 0);   // authoritative count via L2
        g_done[img] = 0;                        // reset for next replay
    }
    __syncthreads();

    int total = misc[0];
    if (total > CANDCAP) total = CANDCAP;

    // ---- gather (coalesced, L2-hot) ----
    for (int k = tid; k < total; k += FS_T)
        skey[k] = g_cand1[img * CANDCAP + k];
    for (int k = total + tid; k < CANDCAP; k += FS_T) skey[k] = 0ull;
    hist[tid] = 0;
    if (tid == 0) g_cnt1[img] = 0;              // reset for next replay
    __syncthreads();

    // ---- histogram of conf bits (monotonic bins) ----
    for (int k = tid; k < total; k += FS_T) {
        u32 bits = (u32)(skey[k] >> 32);
        int b = (int)((bits - 0x3F000000u) >> 13);
        b = b < 0 ? 0 : (b > 1023 ? 1023 : b);
        atomicAdd(&hist[b], 1u);
    }
    __syncthreads();

    // ---- hierarchical suffix sums ----
    {
        u32 x = hist[tid];
        #pragma unroll
        for (int d = 1; d < 32; d <<= 1) {
            u32 y = __shfl_down_sync(0xFFFFFFFFu, x, d);
            if (lane + d < 32) x += y;
        }
        if (lane == 0) wsum[warp] = x;
        __syncthreads();
        if (warp == 0) {
            u32 t = wsum[lane];
            u32 sx = t;
            #pragma unroll
            for (int d = 1; d < 32; d <<= 1) {
                u32 y = __shfl_down_sync(0xFFFFFFFFu, sx, d);
                if (lane + d < 32) sx += y;
            }
            woff[lane] = sx - t;
        }
        __syncthreads();
        hist[tid] = x + woff[warp];
        __syncthreads();
    }

    int need = total < TOPK ? total : TOPK;
    if ((int)hist[tid] >= need && (tid == 1023 || (int)hist[tid + 1] < need))
        misc[1] = tid;
    if (tid == 0) misc[2] = 0;
    __syncthreads();

    int T = misc[1];
    int kept = (int)hist[T];
    bool fallback = (kept > SEL_N);

    u64 mykey;
    if (!fallback) {
        // warp-aggregated compaction
        for (int k = tid; k < CANDCAP; k += FS_T) {
            bool take = false;
            u64 key = 0ull;
            if (k < total) {
                key = skey[k];
                u32 bits = (u32)(key >> 32);
                int b = (int)((bits - 0x3F000000u) >> 13);
                b = b < 0 ? 0 : (b > 1023 ? 1023 : b);
                take = (b >= T);
            }
            u32 bal = __ballot_sync(0xFFFFFFFFu, take);
            if (bal) {
                int nset = __popc(bal);
                int base_pos;
                if (lane == __ffs(bal) - 1)
                    base_pos = atomicAdd(&misc[2], nset);
                base_pos = __shfl_sync(0xFFFFFFFFu, base_pos, __ffs(bal) - 1);
                if (take) {
                    int off = __popc(bal & ((1u << lane) - 1u));
                    skey2[base_pos + off] = key;
                }
            }
        }
        __syncthreads();
        for (int k = kept + tid; k < SEL_N; k += FS_T) skey2[k] = 0ull;
        __syncthreads();

        // ---- double-buffered hybrid bitonic: 1 elem/thread ----
        u64 v = skey2[tid];
        #pragma unroll
        for (int k = 2; k <= 32; k <<= 1) {
            #pragma unroll
            for (int j = k >> 1; j > 0; j >>= 1) {
                u64 o = __shfl_xor_sync(0xFFFFFFFFu, v, j);
                bool keep_max = ((tid & j) == 0) == ((tid & k) == 0);
                bool vbig = v > o;
                v = (keep_max == vbig) ? v : o;
            }
        }
        u64* bufs[2] = { skey2, skey3 };
        int cur = 0;
        bufs[cur][tid] = v;
        __syncthreads();
        #pragma unroll
        for (int k = 64; k <= SEL_N; k <<= 1) {
            for (int j = k >> 1; j >= 32; j >>= 1) {
                u64 o = bufs[cur][tid ^ j];
                bool keep_max = ((tid & j) == 0) == ((tid & k) == 0);
                bool vbig = v > o;
                v = (keep_max == vbig) ? v : o;
                bufs[cur ^ 1][tid] = v;
                cur ^= 1;
                __syncthreads();
            }
            #pragma unroll
            for (int j = 16; j > 0; j >>= 1) {
                u64 o = __shfl_xor_sync(0xFFFFFFFFu, v, j);
                bool keep_max = ((tid & j) == 0) == ((tid & k) == 0);
                bool vbig = v > o;
                v = (keep_max == vbig) ? v : o;
            }
            if (k < SEL_N) {
                bufs[cur][tid] = v;
                __syncthreads();
            }
        }
        mykey = v;
    } else {
        u64* sbuf = skey;
        const int n = CANDCAP;
        __syncthreads();
        for (int k = 2; k <= n; k <<= 1) {
            for (int j = k >> 1; j > 0; j >>= 1) {
                for (int q = 0; q < n; q += FS_T) {
                    int i = tid + q;
                    int ixj = i ^ j;
                    if (ixj > i) {
                        u64 a = sbuf[i], b = sbuf[ixj];
                        if (((i & k) == 0) ? (a < b) : (a > b)) {
                            sbuf[i] = b; sbuf[ixj] = a;
                        }
                    }
                }
                __syncthreads();
            }
        }
        mykey = sbuf[tid];
    }

    // ---- extract top-1000 ----
    if (tid < TOPK) {
        u64 key = mykey;
        float4 b; float sc, ar; int idx;
        if ((key >> 32) != 0ull) {
            idx = (int)(0xFFFFFFFFu - (u32)(key & 0xFFFFFFFFull));
            sc  = __uint_as_float((u32)(key >> 32));
            float x = p[idx * PRED_C + 0];
            float y = p[idx * PRED_C + 1];
            float w = p[idx * PRED_C + 2];
            float h = p[idx * PRED_C + 3];
            float hw = __fmul_rn(w, 0.5f);
            float hh = __fmul_rn(h, 0.5f);
            b = make_float4(__fsub_rn(x, hw), __fsub_rn(y, hh),
                            __fadd_rn(x, hw), __fadd_rn(y, hh));
            ar = __fmul_rn(__fsub_rn(b.z, b.x), __fsub_rn(b.w, b.y));
        } else {
            idx = -1; sc = -1.0f; ar = 0.0f;
            b = make_float4(0.f, 0.f, 0.f, 0.f);
        }
        g_box  [img * 1024 + tid] = b;
        g_score[img * 1024 + tid] = sc;
        g_area [img * 1024 + tid] = ar;
        g_idx  [img * 1024 + tid] = idx;
    }
}

// ============================================================
// 2) mask: balanced upper-triangle (row, word) tasks (R9 verbatim)
// ============================================================
__global__ __launch_bounds__(MASK_T)
void k_mask()
{
    __shared__ float4 sbox[TOPK];
    __shared__ float  sarea[TOPK];

    const int img  = blockIdx.x;
    const int tid  = threadIdx.x;
    const int lane = tid & 31;
    const int gw   = blockIdx.y * (MASK_T / 32) + (tid >> 5);

    for (int i = tid; i < TOPK; i += MASK_T) {
        sbox[i]  = g_box [img * 1024 + i];
        sarea[i] = g_area[img * 1024 + i];
    }
    __syncthreads();

    u32* gm = g_mask + (size_t)img * TOPK * MASKW;

    int u    = (int)(((long long)gw * TASKS) / NWARPS_M);
    int uend = (int)(((long long)(gw + 1) * TASKS) / NWARPS_M);

    int w = 0, acc = 0;
    while (true) {
        int cw = 32 * w + 32; if (cw > TOPK) cw = TOPK;
        if (acc + cw > u) break;
        acc += cw; w++;
    }
    int i  = u - acc;
    int cw = 32 * w + 32; if (cw > TOPK) cw = TOPK;

    int j = w * 32 + lane;
    bool jv = (j < TOPK);
    float4 bj = sbox[jv ? j : 0];
    float  aj = sarea[jv ? j : 0];

    for (; u < uend; ++u) {
        if (i == cw) {
            w++; i = 0;
            cw = 32 * w + 32; if (cw > TOPK) cw = TOPK;
            j = w * 32 + lane;
            jv = (j < TOPK);
            bj = sbox[jv ? j : 0];
            aj = sarea[jv ? j : 0];
        }
        float4 bi = sbox[i];
        float  ai = sarea[i];
        float lx = fmaxf(bi.x, bj.x);
        float ly = fmaxf(bi.y, bj.y);
        float rx = fminf(bi.z, bj.z);
        float ry = fminf(bi.w, bj.w);
        float iw = fmaxf(__fsub_rn(rx, lx), 0.0f);
        float ih = fmaxf(__fsub_rn(ry, ly), 0.0f);
        float inter = __fmul_rn(iw, ih);
        bool sup = false;
        if (j > i && jv && inter > 0.0f) {
            float denom = __fadd_rn(__fsub_rn(__fadd_rn(ai, aj), inter), 1e-7f);
            sup = (__fdiv_rn(inter, denom) > IOU_T);
        }
        u32 word = __ballot_sync(0xFFFFFFFFu, sup);
        if (lane == 0) gm[i * MASKW + w] = word;
        i++;
    }
}

// ============================================================
// 3) sweep: pipelined resolve/accumulate (R9 verbatim)
// ============================================================
#define STEP(b, d) { u32 s = (u32)((int)(alive << (31 - (b))) >> 31); \
                     alive &= ~((d) & s); }

__global__ __launch_bounds__(SWEEP_T, 1)
void k_sweep(const float* __restrict__ pred,
             float* __restrict__ out,
             float* __restrict__ keep_out)
{
    extern __shared__ unsigned char sraw[];
    u32* smask  = (u32*)sraw;                 // 1024*32 (pad rows zeroed)
    u32* sdiag  = smask + 1024 * MASKW;       // 1024
    u32* ssup   = sdiag + 1024;               // 1024
    u32* svalid = ssup + 1024;                // 32
    u32* skeep  = svalid + 32;                // 32
    u32* sremv  = skeep + 32;                 // 32

    const int img  = blockIdx.x;
    const int tid  = threadIdx.x;
    const int warp = tid >> 5, lane = tid & 31;

    {
        const uint4* src = (const uint4*)(g_mask + (size_t)img * TOPK * MASKW);
        uint4* dst = (uint4*)smask;
        for (int k = tid; k < TOPK * MASKW / 4; k += SWEEP_T) dst[k] = src[k];
        for (int k = TOPK * MASKW + tid; k < 1024 * MASKW; k += SWEEP_T) smask[k] = 0;
    }

    for (int k = 0; k < 1024; k += SWEEP_T) {
        int t = k + tid;
        float sc = (t < TOPK) ? g_score[img * 1024 + t] : -1.0f;
        u32 vb = __ballot_sync(0xFFFFFFFFu, sc > CONF_T);
        if (lane == 0) svalid[t >> 5] = vb;
    }
    if (tid < 32) sremv[tid] = 0;
    __syncthreads();

    for (int t = tid; t < 1024; t += SWEEP_T) {
        int c = t >> 5;
        sdiag[t] = smask[t * 32 + c];
        ssup[t]  = (c + 1 < 32) ? smask[t * 32 + c + 1] : 0u;
    }
    __syncthreads();

    u32 carry = 0;
    for (int w = 0; w < 32; w++) {
        if (warp == 0) {
            const uint4* dq = (const uint4*)(sdiag + w * 32);
            uint4 q0 = dq[0], q1 = dq[1], q2 = dq[2], q3 = dq[3];
            uint4 q4 = dq[4], q5 = dq[5], q6 = dq[6], q7 = dq[7];
            u32 alive = svalid[w] & ~(sremv[w] | carry);
            STEP( 0, q0.x) STEP( 1, q0.y) STEP( 2, q0.z) STEP( 3, q0.w)
            STEP( 4, q1.x) STEP( 5, q1.y) STEP( 6, q1.z) STEP( 7, q1.w)
            STEP( 8, q2.x) STEP( 9, q2.y) STEP(10, q2.z) STEP(11, q2.w)
            STEP(12, q3.x) STEP(13, q3.y) STEP(14, q3.z) STEP(15, q3.w)
            STEP(16, q4.x) STEP(17, q4.y) STEP(18, q4.z) STEP(19, q4.w)
            STEP(20, q5.x) STEP(21, q5.y) STEP(22, q5.z) STEP(23, q5.w)
            STEP(24, q6.x) STEP(25, q6.y) STEP(26, q6.z) STEP(27, q6.w)
            STEP(28, q7.x) STEP(29, q7.y) STEP(30, q7.z) STEP(31, q7.w)
            if (lane == 0) skeep[w] = alive;
            u32 contrib = ssup[w * 32 + lane] & (0u - ((alive >> lane) & 1u));
            carry = __reduce_or_sync(0xFFFFFFFFu, contrib);
        } else if (w > 0) {
            u32 a = skeep[w - 1];
            u32 partial = 0;
            for (int b = warp - 1; b < 32; b += 15) {
                if ((a >> b) & 1u)
                    partial |= smask[((w - 1) * 32 + b) * 32 + lane];
            }
            if (partial) atomicOr(&sremv[lane], partial);
        }
        __syncthreads();
    }

    const float* p = pred + (size_t)img * NPRED * PRED_C;
    for (int t = tid; t < TOPK; t += SWEEP_T) {
        bool kp = (skeep[t >> 5] >> (t & 31)) & 1u;
        float o0=0.f,o1=0.f,o2=0.f,o3=0.f,o4=0.f,o6=0.f,o7=0.f,o8=0.f;
        if (kp) {
            float4 b = g_box[img * 1024 + t];
            o0 = b.x; o1 = b.y; o2 = b.z; o3 = b.w;
            o4 = g_score[img * 1024 + t];
            int idx = g_idx[img * 1024 + t];
            o6 = p[idx * PRED_C + 6];
            o7 = p[idx * PRED_C + 7];
            o8 = p[idx * PRED_C + 8];
        }
        float* orow = out + ((size_t)img * TOPK + t) * PRED_C;
        orow[0]=o0; orow[1]=o1; orow[2]=o2; orow[3]=o3;
        orow[4]=o4; orow[5]=0.0f;
        orow[6]=o6; orow[7]=o7; orow[8]=o8;
        keep_out[(size_t)img * TOPK + t] = kp ? 1.0f : 0.0f;
    }
}

extern "C" void kernel_launch(void* const* d_in, const int* in_sizes, int n_in,
                              void* d_out, int out_size)
{
    const float* pred = (const float*)d_in[0];
    int B = in_sizes[0] / (NPRED * PRED_C);

    float* out  = (float*)d_out;
    float* keep = out + (size_t)B * TOPK * PRED_C;

    size_t smemFS    = (size_t)CANDCAP * 8 + (size_t)SEL_N * 8 * 2 +
                       1024 * 4 + 64 * 4 + 32;
    size_t smemSweep = (size_t)1024 * MASKW * 4 + 2 * 1024 * 4 + 128 * 4;

    static bool attr_set = false;
    if (!attr_set) {
        cudaFuncSetAttribute(k_filtersort,
                             cudaFuncAttributeMaxDynamicSharedMemorySize,
                             (int)smemFS);
        cudaFuncSetAttribute(k_sweep,
                             cudaFuncAttributeMaxDynamicSharedMemorySize,
                             (int)smemSweep);
        attr_set = true;
    }

    k_filtersort<<<dim3(B, NSLICE), FS_T, smemFS>>>(pred);
    k_mask<<<dim3(B, MSLICES), MASK_T>>>();
    k_sweep<<<B, SWEEP_T, smemSweep>>>(pred, out, keep);
}

// round 15
// speedup vs baseline: 2.1869x; 1.2004x over previous
#include <cuda_runtime.h>
#include <stdint.h>

#define NPRED    25200
#define PRED_C   9
#define TOPK     1000
#define CONF_T   0.7f
#define IOU_T    0.45f
#define MASKW    32
#define BMAX     32

#define NSLICE   25
#define ROWS_SL  1008
#define FILT_T   256
#define SLICE_F4 2268          // 1008*9/4 float4s per slice

#define CANDCAP  4096
#define SEL_N    1024
#define SORT_T   1024

#define MSLICES  16
#define MASK_T   256
#define NWARPS_M (MSLICES * (MASK_T / 32))    // 128 warps per image
#define TASKS    16872                        // sum_w min(1000, 32w+32)

#define SWEEP_T  512

typedef unsigned long long u64;
typedef unsigned int u32;

// ---------------- global scratch ----------------
__device__ int    g_cnt [BMAX * NSLICE];
__device__ u64    g_cand[BMAX * NSLICE * ROWS_SL];
__device__ float4 g_box [BMAX * 1024];
__device__ float  g_score[BMAX * 1024];
__device__ float  g_area[BMAX * 1024];
__device__ int    g_idx [BMAX * 1024];
__device__ u32    g_mask[BMAX * TOPK * MASKW];   // lower-tri words never written (stay 0)

// ============================================================
// 1) filter: full-chip pass, coalesced float4 staging via smem
// ============================================================
__global__ __launch_bounds__(FILT_T)
void k_filter(const float* __restrict__ pred)
{
    __shared__ float sdata[ROWS_SL * PRED_C];   // 36288 B
    __shared__ u64 buf[ROWS_SL];                // 8064 B
    __shared__ int cnt;

    const int img   = blockIdx.x;
    const int slice = blockIdx.y;
    const int tid   = threadIdx.x;

    if (tid == 0) cnt = 0;

    // coalesced staging: 2268 float4 loads (slice base is 16B-aligned)
    {
        const float4* src = (const float4*)(pred +
            (size_t)img * NPRED * PRED_C + (size_t)slice * ROWS_SL * PRED_C);
        float4* dst = (float4*)sdata;
        #pragma unroll
        for (int r = 0; r < 9; r++) {
            int k = tid + r * FILT_T;
            if (k < SLICE_F4) dst[k] = src[k];
        }
    }
    __syncthreads();

    const int base = slice * ROWS_SL;
    #pragma unroll
    for (int r = 0; r < 4; r++) {
        int row = tid + r * FILT_T;
        if (row < ROWS_SL) {
            float obj = sdata[row * PRED_C + 4];
            float cls = sdata[row * PRED_C + 5];
            float conf = __fmul_rn(obj, cls);
            if (obj > CONF_T && conf > CONF_T) {
                int i = base + row;
                int pos = atomicAdd(&cnt, 1);
                buf[pos] = ((u64)__float_as_uint(conf) << 32) |
                           (u64)(0xFFFFFFFFu - (u32)i);
            }
        }
    }
    __syncthreads();

    int n = cnt;
    if (tid == 0) g_cnt[img * NSLICE + slice] = n;
    u64* dst = g_cand + (size_t)(img * NSLICE + slice) * ROWS_SL;
    for (int k = tid; k < n; k += FILT_T) dst[k] = buf[k];
}

// ============================================================
// 2) sort: parallel gather, histogram select, warp-agg extract,
//    double-buffered hybrid bitonic   (R9 verbatim)
// ============================================================
__global__ __launch_bounds__(SORT_T, 1)
void k_sort(const float* __restrict__ pred)
{
    extern __shared__ unsigned char sraw[];
    u64* skey  = (u64*)sraw;                          // CANDCAP
    u64* skey2 = skey + CANDCAP;                      // SEL_N (buffer A)
    u64* skey3 = skey2 + SEL_N;                       // SEL_N (buffer B)
    u32* hist  = (u32*)(skey3 + SEL_N);               // 1024
    u32* wsum  = hist + 1024;                         // 32
    u32* woff  = wsum + 32;                           // 32
    int* spfx  = (int*)(woff + 32);                   // 33
    int* misc  = spfx + 33;                           // [0]=total [1]=T [2]=kept

    const int img = blockIdx.x;
    const int tid = threadIdx.x;
    const int lane = tid & 31, warp = tid >> 5;
    const float* p = pred + (size_t)img * NPRED * PRED_C;

    if (tid < 32) {
        int c = (tid < NSLICE) ? g_cnt[img * NSLICE + tid] : 0;
        int x = c;
        #pragma unroll
        for (int d = 1; d < 32; d <<= 1) {
            int y = __shfl_up_sync(0xFFFFFFFFu, x, d);
            if ((tid & 31) >= d) x += y;
        }
        spfx[tid + 1] = x;
        if (tid == 0) spfx[0] = 0;
        if (tid == 31) misc[0] = x;
    }
    __syncthreads();

    int total = misc[0];
    if (total > CANDCAP) total = CANDCAP;

    // parallel gather: thread k binary-searches its slice
    for (int k = tid; k < total; k += SORT_T) {
        int lo = 0, hi = NSLICE;
        #pragma unroll
        for (int it = 0; it < 5; it++) {
            int mid = (lo + hi) >> 1;
            if (spfx[mid] <= k) lo = mid; else hi = mid;
        }
        skey[k] = g_cand[(size_t)(img * NSLICE + lo) * ROWS_SL + (k - spfx[lo])];
    }
    for (int k = total + tid; k < CANDCAP; k += SORT_T) skey[k] = 0ull;
    hist[tid] = 0;
    __syncthreads();

    for (int k = tid; k < total; k += SORT_T) {
        u32 bits = (u32)(skey[k] >> 32);
        int b = (int)((bits - 0x3F000000u) >> 13);
        b = b < 0 ? 0 : (b > 1023 ? 1023 : b);
        atomicAdd(&hist[b], 1u);
    }
    __syncthreads();

    // hierarchical suffix sums
    {
        u32 x = hist[tid];
        #pragma unroll
        for (int d = 1; d < 32; d <<= 1) {
            u32 y = __shfl_down_sync(0xFFFFFFFFu, x, d);
            if (lane + d < 32) x += y;
        }
        if (lane == 0) wsum[warp] = x;
        __syncthreads();
        if (warp == 0) {
            u32 t = wsum[lane];
            u32 sx = t;
            #pragma unroll
            for (int d = 1; d < 32; d <<= 1) {
                u32 y = __shfl_down_sync(0xFFFFFFFFu, sx, d);
                if (lane + d < 32) sx += y;
            }
            woff[lane] = sx - t;
        }
        __syncthreads();
        hist[tid] = x + woff[warp];
        __syncthreads();
    }

    int need = total < TOPK ? total : TOPK;
    if ((int)hist[tid] >= need && (tid == 1023 || (int)hist[tid + 1] < need))
        misc[1] = tid;
    if (tid == 0) misc[2] = 0;
    __syncthreads();

    int T = misc[1];
    int kept = (int)hist[T];
    bool fallback = (kept > SEL_N);

    u64 mykey;
    if (!fallback) {
        for (int k = tid; k < CANDCAP; k += SORT_T) {
            bool take = false;
            u64 key = 0ull;
            if (k < total) {
                key = skey[k];
                u32 bits = (u32)(key >> 32);
                int b = (int)((bits - 0x3F000000u) >> 13);
                b = b < 0 ? 0 : (b > 1023 ? 1023 : b);
                take = (b >= T);
            }
            u32 bal = __ballot_sync(0xFFFFFFFFu, take);
            if (bal) {
                int nset = __popc(bal);
                int base_pos;
                if (lane == __ffs(bal) - 1)
                    base_pos = atomicAdd(&misc[2], nset);
                base_pos = __shfl_sync(0xFFFFFFFFu, base_pos, __ffs(bal) - 1);
                if (take) {
                    int off = __popc(bal & ((1u << lane) - 1u));
                    skey2[base_pos + off] = key;
                }
            }
        }
        __syncthreads();
        for (int k = kept + tid; k < SEL_N; k += SORT_T) skey2[k] = 0ull;
        __syncthreads();

        u64 v = skey2[tid];
        #pragma unroll
        for (int k = 2; k <= 32; k <<= 1) {
            #pragma unroll
            for (int j = k >> 1; j > 0; j >>= 1) {
                u64 o = __shfl_xor_sync(0xFFFFFFFFu, v, j);
                bool keep_max = ((tid & j) == 0) == ((tid & k) == 0);
                bool vbig = v > o;
                v = (keep_max == vbig) ? v : o;
            }
        }
        u64* bufs[2] = { skey2, skey3 };
        int cur = 0;
        bufs[cur][tid] = v;
        __syncthreads();
        #pragma unroll
        for (int k = 64; k <= SEL_N; k <<= 1) {
            for (int j = k >> 1; j >= 32; j >>= 1) {
                u64 o = bufs[cur][tid ^ j];
                bool keep_max = ((tid & j) == 0) == ((tid & k) == 0);
                bool vbig = v > o;
                v = (keep_max == vbig) ? v : o;
                bufs[cur ^ 1][tid] = v;
                cur ^= 1;
                __syncthreads();
            }
            #pragma unroll
            for (int j = 16; j > 0; j >>= 1) {
                u64 o = __shfl_xor_sync(0xFFFFFFFFu, v, j);
                bool keep_max = ((tid & j) == 0) == ((tid & k) == 0);
                bool vbig = v > o;
                v = (keep_max == vbig) ? v : o;
            }
            if (k < SEL_N) {
                bufs[cur][tid] = v;
                __syncthreads();
            }
        }
        mykey = v;
    } else {
        u64* sbuf = skey;
        const int n = CANDCAP;
        __syncthreads();
        for (int k = 2; k <= n; k <<= 1) {
            for (int j = k >> 1; j > 0; j >>= 1) {
                for (int q = 0; q < n; q += SORT_T) {
                    int i = tid + q;
                    int ixj = i ^ j;
                    if (ixj > i) {
                        u64 a = sbuf[i], b = sbuf[ixj];
                        if (((i & k) == 0) ? (a < b) : (a > b)) {
                            sbuf[i] = b; sbuf[ixj] = a;
                        }
                    }
                }
                __syncthreads();
            }
        }
        mykey = sbuf[tid];
    }

    if (tid < TOPK) {
        u64 key = mykey;
        float4 b; float sc, ar; int idx;
        if ((key >> 32) != 0ull) {
            idx = (int)(0xFFFFFFFFu - (u32)(key & 0xFFFFFFFFull));
            sc  = __uint_as_float((u32)(key >> 32));
            float x = p[idx * PRED_C + 0];
            float y = p[idx * PRED_C + 1];
            float w = p[idx * PRED_C + 2];
            float h = p[idx * PRED_C + 3];
            float hw = __fmul_rn(w, 0.5f);
            float hh = __fmul_rn(h, 0.5f);
            b = make_float4(__fsub_rn(x, hw), __fsub_rn(y, hh),
                            __fadd_rn(x, hw), __fadd_rn(y, hh));
            ar = __fmul_rn(__fsub_rn(b.z, b.x), __fsub_rn(b.w, b.y));
        } else {
            idx = -1; sc = -1.0f; ar = 0.0f;
            b = make_float4(0.f, 0.f, 0.f, 0.f);
        }
        g_box  [img * 1024 + tid] = b;
        g_score[img * 1024 + tid] = sc;
        g_area [img * 1024 + tid] = ar;
        g_idx  [img * 1024 + tid] = idx;
    }
}

// ============================================================
// 3) mask: balanced upper-triangle (row, word) tasks (R9 verbatim)
// ============================================================
__global__ __launch_bounds__(MASK_T)
void k_mask()
{
    __shared__ float4 sbox[TOPK];
    __shared__ float  sarea[TOPK];

    const int img  = blockIdx.x;
    const int tid  = threadIdx.x;
    const int lane = tid & 31;
    const int gw   = blockIdx.y * (MASK_T / 32) + (tid >> 5);

    for (int i = tid; i < TOPK; i += MASK_T) {
        sbox[i]  = g_box [img * 1024 + i];
        sarea[i] = g_area[img * 1024 + i];
    }
    __syncthreads();

    u32* gm = g_mask + (size_t)img * TOPK * MASKW;

    int u    = (int)(((long long)gw * TASKS) / NWARPS_M);
    int uend = (int)(((long long)(gw + 1) * TASKS) / NWARPS_M);

    int w = 0, acc = 0;
    while (true) {
        int cw = 32 * w + 32; if (cw > TOPK) cw = TOPK;
        if (acc + cw > u) break;
        acc += cw; w++;
    }
    int i  = u - acc;
    int cw = 32 * w + 32; if (cw > TOPK) cw = TOPK;

    int j = w * 32 + lane;
    bool jv = (j < TOPK);
    float4 bj = sbox[jv ? j : 0];
    float  aj = sarea[jv ? j : 0];

    for (; u < uend; ++u) {
        if (i == cw) {
            w++; i = 0;
            cw = 32 * w + 32; if (cw > TOPK) cw = TOPK;
            j = w * 32 + lane;
            jv = (j < TOPK);
            bj = sbox[jv ? j : 0];
            aj = sarea[jv ? j : 0];
        }
        float4 bi = sbox[i];
        float  ai = sarea[i];
        float lx = fmaxf(bi.x, bj.x);
        float ly = fmaxf(bi.y, bj.y);
        float rx = fminf(bi.z, bj.z);
        float ry = fminf(bi.w, bj.w);
        float iw = fmaxf(__fsub_rn(rx, lx), 0.0f);
        float ih = fmaxf(__fsub_rn(ry, ly), 0.0f);
        float inter = __fmul_rn(iw, ih);
        bool sup = false;
        if (j > i && jv && inter > 0.0f) {
            float denom = __fadd_rn(__fsub_rn(__fadd_rn(ai, aj), inter), 1e-7f);
            sup = (__fdiv_rn(inter, denom) > IOU_T);
        }
        u32 word = __ballot_sync(0xFFFFFFFFu, sup);
        if (lane == 0) gm[i * MASKW + w] = word;
        i++;
    }
}

// ============================================================
// 4) sweep: pipelined resolve/accumulate (R9 verbatim)
// ============================================================
#define STEP(b, d) { u32 s = (u32)((int)(alive << (31 - (b))) >> 31); \
                     alive &= ~((d) & s); }

__global__ __launch_bounds__(SWEEP_T, 1)
void k_sweep(const float* __restrict__ pred,
             float* __restrict__ out,
             float* __restrict__ keep_out)
{
    extern __shared__ unsigned char sraw[];
    u32* smask  = (u32*)sraw;                 // 1024*32 (pad rows zeroed)
    u32* sdiag  = smask + 1024 * MASKW;       // 1024
    u32* ssup   = sdiag + 1024;               // 1024
    u32* svalid = ssup + 1024;                // 32
    u32* skeep  = svalid + 32;                // 32
    u32* sremv  = skeep + 32;                 // 32

    const int img  = blockIdx.x;
    const int tid  = threadIdx.x;
    const int warp = tid >> 5, lane = tid & 31;

    {
        const uint4* src = (const uint4*)(g_mask + (size_t)img * TOPK * MASKW);
        uint4* dst = (uint4*)smask;
        for (int k = tid; k < TOPK * MASKW / 4; k += SWEEP_T) dst[k] = src[k];
        for (int k = TOPK * MASKW + tid; k < 1024 * MASKW; k += SWEEP_T) smask[k] = 0;
    }

    for (int k = 0; k < 1024; k += SWEEP_T) {
        int t = k + tid;
        float sc = (t < TOPK) ? g_score[img * 1024 + t] : -1.0f;
        u32 vb = __ballot_sync(0xFFFFFFFFu, sc > CONF_T);
        if (lane == 0) svalid[t >> 5] = vb;
    }
    if (tid < 32) sremv[tid] = 0;
    __syncthreads();

    for (int t = tid; t < 1024; t += SWEEP_T) {
        int c = t >> 5;
        sdiag[t] = smask[t * 32 + c];
        ssup[t]  = (c + 1 < 32) ? smask[t * 32 + c + 1] : 0u;
    }
    __syncthreads();

    u32 carry = 0;
    for (int w = 0; w < 32; w++) {
        if (warp == 0) {
            const uint4* dq = (const uint4*)(sdiag + w * 32);
            uint4 q0 = dq[0], q1 = dq[1], q2 = dq[2], q3 = dq[3];
            uint4 q4 = dq[4], q5 = dq[5], q6 = dq[6], q7 = dq[7];
            u32 alive = svalid[w] & ~(sremv[w] | carry);
            STEP( 0, q0.x) STEP( 1, q0.y) STEP( 2, q0.z) STEP( 3, q0.w)
            STEP( 4, q1.x) STEP( 5, q1.y) STEP( 6, q1.z) STEP( 7, q1.w)
            STEP( 8, q2.x) STEP( 9, q2.y) STEP(10, q2.z) STEP(11, q2.w)
            STEP(12, q3.x) STEP(13, q3.y) STEP(14, q3.z) STEP(15, q3.w)
            STEP(16, q4.x) STEP(17, q4.y) STEP(18, q4.z) STEP(19, q4.w)
            STEP(20, q5.x) STEP(21, q5.y) STEP(22, q5.z) STEP(23, q5.w)
            STEP(24, q6.x) STEP(25, q6.y) STEP(26, q6.z) STEP(27, q6.w)
            STEP(28, q7.x) STEP(29, q7.y) STEP(30, q7.z) STEP(31, q7.w)
            if (lane == 0) skeep[w] = alive;
            u32 contrib = ssup[w * 32 + lane] & (0u - ((alive >> lane) & 1u));
            carry = __reduce_or_sync(0xFFFFFFFFu, contrib);
        } else if (w > 0) {
            u32 a = skeep[w - 1];
            u32 partial = 0;
            for (int b = warp - 1; b < 32; b += 15) {
                if ((a >> b) & 1u)
                    partial |= smask[((w - 1) * 32 + b) * 32 + lane];
            }
            if (partial) atomicOr(&sremv[lane], partial);
        }
        __syncthreads();
    }

    const float* p = pred + (size_t)img * NPRED * PRED_C;
    for (int t = tid; t < TOPK; t += SWEEP_T) {
        bool kp = (skeep[t >> 5] >> (t & 31)) & 1u;
        float o0=0.f,o1=0.f,o2=0.f,o3=0.f,o4=0.f,o6=0.f,o7=0.f,o8=0.f;
        if (kp) {
            float4 b = g_box[img * 1024 + t];
            o0 = b.x; o1 = b.y; o2 = b.z; o3 = b.w;
            o4 = g_score[img * 1024 + t];
            int idx = g_idx[img * 1024 + t];
            o6 = p[idx * PRED_C + 6];
            o7 = p[idx * PRED_C + 7];
            o8 = p[idx * PRED_C + 8];
        }
        float* orow = out + ((size_t)img * TOPK + t) * PRED_C;
        orow[0]=o0; orow[1]=o1; orow[2]=o2; orow[3]=o3;
        orow[4]=o4; orow[5]=0.0f;
        orow[6]=o6; orow[7]=o7; orow[8]=o8;
        keep_out[(size_t)img * TOPK + t] = kp ? 1.0f : 0.0f;
    }
}

extern "C" void kernel_launch(void* const* d_in, const int* in_sizes, int n_in,
                              void* d_out, int out_size)
{
    const float* pred = (const float*)d_in[0];
    int B = in_sizes[0] / (NPRED * PRED_C);

    float* out  = (float*)d_out;
    float* keep = out + (size_t)B * TOPK * PRED_C;

    size_t smemSort  = (size_t)CANDCAP * 8 + (size_t)SEL_N * 8 * 2 +
                       1024 * 4 + 64 * 4 + 80 * 4;
    size_t smemSweep = (size_t)1024 * MASKW * 4 + 2 * 1024 * 4 + 128 * 4;

    static bool attr_set = false;
    if (!attr_set) {
        cudaFuncSetAttribute(k_sort,  cudaFuncAttributeMaxDynamicSharedMemorySize,
                             (int)smemSort);
        cudaFuncSetAttribute(k_sweep, cudaFuncAttributeMaxDynamicSharedMemorySize,
                             (int)smemSweep);
        attr_set = true;
    }

    k_filter<<<dim3(B, NSLICE), FILT_T>>>(pred);
    k_sort<<<B, SORT_T, smemSort>>>(pred);
    k_mask<<<dim3(B, MSLICES), MASK_T>>>();
    k_sweep<<<B, SWEEP_T, smemSweep>>>(pred, out, keep);
}

// round 16
// speedup vs baseline: 2.4593x; 1.1246x over previous
#include <cuda_runtime.h>
#include <stdint.h>

#define NPRED    25200
#define PRED_C   9
#define TOPK     1000
#define CONF_T   0.7f
#define IOU_T    0.45f
#define MASKW    32
#define BMAX     32

#define NSLICE   25
#define ROWS_SL  1008
#define FILT_T   256
#define SLICE_F4 2268          // 1008*9/4 float4s per slice

#define CANDCAP  4096
#define SEL_N    1024
#define SORT_T   1024

#define MSLICES  16
#define MASK_T   256
#define NWARPS_M (MSLICES * (MASK_T / 32))    // 128 warps per image
#define TASKS    16872                        // sum_w min(1000, 32w+32)

#define SWEEP_T  1024

typedef unsigned long long u64;
typedef unsigned int u32;

// ---------------- global scratch ----------------
__device__ int    g_cnt [BMAX * NSLICE];
__device__ u64    g_cand[BMAX * NSLICE * ROWS_SL];
__device__ float4 g_box [BMAX * 1024];
__device__ float  g_score[BMAX * 1024];
__device__ float  g_area[BMAX * 1024];
__device__ int    g_idx [BMAX * 1024];
// transposed mask: g_maskT[img][w*1024 + i] = suppression word w of row i.
// lower-triangle (i >= 32w+32) and pad rows never written -> stay 0.
__device__ u32    g_maskT[BMAX * 32 * 1024];

// ============================================================
// 1) filter: full-chip pass, coalesced float4 staging via smem
// ============================================================
__global__ __launch_bounds__(FILT_T)
void k_filter(const float* __restrict__ pred)
{
    __shared__ float sdata[ROWS_SL * PRED_C];   // 36288 B
    __shared__ u64 buf[ROWS_SL];                // 8064 B
    __shared__ int cnt;

    const int img   = blockIdx.x;
    const int slice = blockIdx.y;
    const int tid   = threadIdx.x;

    if (tid == 0) cnt = 0;

    {
        const float4* src = (const float4*)(pred +
            (size_t)img * NPRED * PRED_C + (size_t)slice * ROWS_SL * PRED_C);
        float4* dst = (float4*)sdata;
        #pragma unroll
        for (int r = 0; r < 9; r++) {
            int k = tid + r * FILT_T;
            if (k < SLICE_F4) dst[k] = src[k];
        }
    }
    __syncthreads();

    const int base = slice * ROWS_SL;
    #pragma unroll
    for (int r = 0; r < 4; r++) {
        int row = tid + r * FILT_T;
        if (row < ROWS_SL) {
            float obj = sdata[row * PRED_C + 4];
            float cls = sdata[row * PRED_C + 5];
            float conf = __fmul_rn(obj, cls);
            if (obj > CONF_T && conf > CONF_T) {
                int i = base + row;
                int pos = atomicAdd(&cnt, 1);
                buf[pos] = ((u64)__float_as_uint(conf) << 32) |
                           (u64)(0xFFFFFFFFu - (u32)i);
            }
        }
    }
    __syncthreads();

    int n = cnt;
    if (tid == 0) g_cnt[img * NSLICE + slice] = n;
    u64* dst = g_cand + (size_t)(img * NSLICE + slice) * ROWS_SL;
    for (int k = tid; k < n; k += FILT_T) dst[k] = buf[k];
}

// ============================================================
// 2) sort: parallel gather, histogram select, warp-agg extract,
//    double-buffered hybrid bitonic
// ============================================================
__global__ __launch_bounds__(SORT_T, 1)
void k_sort(const float* __restrict__ pred)
{
    extern __shared__ unsigned char sraw[];
    u64* skey  = (u64*)sraw;                          // CANDCAP
    u64* skey2 = skey + CANDCAP;                      // SEL_N (buffer A)
    u64* skey3 = skey2 + SEL_N;                       // SEL_N (buffer B)
    u32* hist  = (u32*)(skey3 + SEL_N);               // 1024
    u32* wsum  = hist + 1024;                         // 32
    u32* woff  = wsum + 32;                           // 32
    int* spfx  = (int*)(woff + 32);                   // 33
    int* misc  = spfx + 33;                           // [0]=total [1]=T [2]=kept

    const int img = blockIdx.x;
    const int tid = threadIdx.x;
    const int lane = tid & 31, warp = tid >> 5;
    const float* p = pred + (size_t)img * NPRED * PRED_C;

    if (tid < 32) {
        int c = (tid < NSLICE) ? g_cnt[img * NSLICE + tid] : 0;
        int x = c;
        #pragma unroll
        for (int d = 1; d < 32; d <<= 1) {
            int y = __shfl_up_sync(0xFFFFFFFFu, x, d);
            if ((tid & 31) >= d) x += y;
        }
        spfx[tid + 1] = x;
        if (tid == 0) spfx[0] = 0;
        if (tid == 31) misc[0] = x;
    }
    __syncthreads();

    int total = misc[0];
    if (total > CANDCAP) total = CANDCAP;

    for (int k = tid; k < total; k += SORT_T) {
        int lo = 0, hi = NSLICE;
        #pragma unroll
        for (int it = 0; it < 5; it++) {
            int mid = (lo + hi) >> 1;
            if (spfx[mid] <= k) lo = mid; else hi = mid;
        }
        skey[k] = g_cand[(size_t)(img * NSLICE + lo) * ROWS_SL + (k - spfx[lo])];
    }
    for (int k = total + tid; k < CANDCAP; k += SORT_T) skey[k] = 0ull;
    hist[tid] = 0;
    __syncthreads();

    for (int k = tid; k < total; k += SORT_T) {
        u32 bits = (u32)(skey[k] >> 32);
        int b = (int)((bits - 0x3F000000u) >> 13);
        b = b < 0 ? 0 : (b > 1023 ? 1023 : b);
        atomicAdd(&hist[b], 1u);
    }
    __syncthreads();

    {
        u32 x = hist[tid];
        #pragma unroll
        for (int d = 1; d < 32; d <<= 1) {
            u32 y = __shfl_down_sync(0xFFFFFFFFu, x, d);
            if (lane + d < 32) x += y;
        }
        if (lane == 0) wsum[warp] = x;
        __syncthreads();
        if (warp == 0) {
            u32 t = wsum[lane];
            u32 sx = t;
            #pragma unroll
            for (int d = 1; d < 32; d <<= 1) {
                u32 y = __shfl_down_sync(0xFFFFFFFFu, sx, d);
                if (lane + d < 32) sx += y;
            }
            woff[lane] = sx - t;
        }
        __syncthreads();
        hist[tid] = x + woff[warp];
        __syncthreads();
    }

    int need = total < TOPK ? total : TOPK;
    if ((int)hist[tid] >= need && (tid == 1023 || (int)hist[tid + 1] < need))
        misc[1] = tid;
    if (tid == 0) misc[2] = 0;
    __syncthreads();

    int T = misc[1];
    int kept = (int)hist[T];
    bool fallback = (kept > SEL_N);

    u64 mykey;
    if (!fallback) {
        for (int k = tid; k < CANDCAP; k += SORT_T) {
            bool take = false;
            u64 key = 0ull;
            if (k < total) {
                key = skey[k];
                u32 bits = (u32)(key >> 32);
                int b = (int)((bits - 0x3F000000u) >> 13);
                b = b < 0 ? 0 : (b > 1023 ? 1023 : b);
                take = (b >= T);
            }
            u32 bal = __ballot_sync(0xFFFFFFFFu, take);
            if (bal) {
                int nset = __popc(bal);
                int base_pos;
                if (lane == __ffs(bal) - 1)
                    base_pos = atomicAdd(&misc[2], nset);
                base_pos = __shfl_sync(0xFFFFFFFFu, base_pos, __ffs(bal) - 1);
                if (take) {
                    int off = __popc(bal & ((1u << lane) - 1u));
                    skey2[base_pos + off] = key;
                }
            }
        }
        __syncthreads();
        for (int k = kept + tid; k < SEL_N; k += SORT_T) skey2[k] = 0ull;
        __syncthreads();

        u64 v = skey2[tid];
        #pragma unroll
        for (int k = 2; k <= 32; k <<= 1) {
            #pragma unroll
            for (int j = k >> 1; j > 0; j >>= 1) {
                u64 o = __shfl_xor_sync(0xFFFFFFFFu, v, j);
                bool keep_max = ((tid & j) == 0) == ((tid & k) == 0);
                bool vbig = v > o;
                v = (keep_max == vbig) ? v : o;
            }
        }
        u64* bufs[2] = { skey2, skey3 };
        int cur = 0;
        bufs[cur][tid] = v;
        __syncthreads();
        #pragma unroll
        for (int k = 64; k <= SEL_N; k <<= 1) {
            for (int j = k >> 1; j >= 32; j >>= 1) {
                u64 o = bufs[cur][tid ^ j];
                bool keep_max = ((tid & j) == 0) == ((tid & k) == 0);
                bool vbig = v > o;
                v = (keep_max == vbig) ? v : o;
                bufs[cur ^ 1][tid] = v;
                cur ^= 1;
                __syncthreads();
            }
            #pragma unroll
            for (int j = 16; j > 0; j >>= 1) {
                u64 o = __shfl_xor_sync(0xFFFFFFFFu, v, j);
                bool keep_max = ((tid & j) == 0) == ((tid & k) == 0);
                bool vbig = v > o;
                v = (keep_max == vbig) ? v : o;
            }
            if (k < SEL_N) {
                bufs[cur][tid] = v;
                __syncthreads();
            }
        }
        mykey = v;
    } else {
        u64* sbuf = skey;
        const int n = CANDCAP;
        __syncthreads();
        for (int k = 2; k <= n; k <<= 1) {
            for (int j = k >> 1; j > 0; j >>= 1) {
                for (int q = 0; q < n; q += SORT_T) {
                    int i = tid + q;
                    int ixj = i ^ j;
                    if (ixj > i) {
                        u64 a = sbuf[i], b = sbuf[ixj];
                        if (((i & k) == 0) ? (a < b) : (a > b)) {
                            sbuf[i] = b; sbuf[ixj] = a;
                        }
                    }
                }
                __syncthreads();
            }
        }
        mykey = sbuf[tid];
    }

    if (tid < TOPK) {
        u64 key = mykey;
        float4 b; float sc, ar; int idx;
        if ((key >> 32) != 0ull) {
            idx = (int)(0xFFFFFFFFu - (u32)(key & 0xFFFFFFFFull));
            sc  = __uint_as_float((u32)(key >> 32));
            float x = p[idx * PRED_C + 0];
            float y = p[idx * PRED_C + 1];
            float w = p[idx * PRED_C + 2];
            float h = p[idx * PRED_C + 3];
            float hw = __fmul_rn(w, 0.5f);
            float hh = __fmul_rn(h, 0.5f);
            b = make_float4(__fsub_rn(x, hw), __fsub_rn(y, hh),
                            __fadd_rn(x, hw), __fadd_rn(y, hh));
            ar = __fmul_rn(__fsub_rn(b.z, b.x), __fsub_rn(b.w, b.y));
        } else {
            idx = -1; sc = -1.0f; ar = 0.0f;
            b = make_float4(0.f, 0.f, 0.f, 0.f);
        }
        g_box  [img * 1024 + tid] = b;
        g_score[img * 1024 + tid] = sc;
        g_area [img * 1024 + tid] = ar;
        g_idx  [img * 1024 + tid] = idx;
    }
}

// ============================================================
// 3) mask: balanced upper-triangle tasks; TRANSPOSED store
// ============================================================
__global__ __launch_bounds__(MASK_T)
void k_mask()
{
    __shared__ float4 sbox[TOPK];
    __shared__ float  sarea[TOPK];

    const int img  = blockIdx.x;
    const int tid  = threadIdx.x;
    const int lane = tid & 31;
    const int gw   = blockIdx.y * (MASK_T / 32) + (tid >> 5);

    for (int i = tid; i < TOPK; i += MASK_T) {
        sbox[i]  = g_box [img * 1024 + i];
        sarea[i] = g_area[img * 1024 + i];
    }
    __syncthreads();

    u32* gmT = g_maskT + (size_t)img * 32 * 1024;

    int u    = (int)(((long long)gw * TASKS) / NWARPS_M);
    int uend = (int)(((long long)(gw + 1) * TASKS) / NWARPS_M);

    int w = 0, acc = 0;
    while (true) {
        int cw = 32 * w + 32; if (cw > TOPK) cw = TOPK;
        if (acc + cw > u) break;
        acc += cw; w++;
    }
    int i  = u - acc;
    int cw = 32 * w + 32; if (cw > TOPK) cw = TOPK;

    int j = w * 32 + lane;
    bool jv = (j < TOPK);
    float4 bj = sbox[jv ? j : 0];
    float  aj = sarea[jv ? j : 0];

    for (; u < uend; ++u) {
        if (i == cw) {
            w++; i = 0;
            cw = 32 * w + 32; if (cw > TOPK) cw = TOPK;
            j = w * 32 + lane;
            jv = (j < TOPK);
            bj = sbox[jv ? j : 0];
            aj = sarea[jv ? j : 0];
        }
        float4 bi = sbox[i];
        float  ai = sarea[i];
        float lx = fmaxf(bi.x, bj.x);
        float ly = fmaxf(bi.y, bj.y);
        float rx = fminf(bi.z, bj.z);
        float ry = fminf(bi.w, bj.w);
        float iw = fmaxf(__fsub_rn(rx, lx), 0.0f);
        float ih = fmaxf(__fsub_rn(ry, ly), 0.0f);
        float inter = __fmul_rn(iw, ih);
        bool sup = false;
        if (j > i && jv && inter > 0.0f) {
            float denom = __fadd_rn(__fsub_rn(__fadd_rn(ai, aj), inter), 1e-7f);
            sup = (__fdiv_rn(inter, denom) > IOU_T);
        }
        u32 word = __ballot_sync(0xFFFFFFFFu, sup);
        if (lane == 0) gmT[w * 1024 + i] = word;
        i++;
    }
}

// ============================================================
// 4) sweep: Jacobi fixed-point iteration (fully parallel)
// ============================================================
__global__ __launch_bounds__(SWEEP_T, 1)
void k_sweep(const float* __restrict__ pred,
             float* __restrict__ out,
             float* __restrict__ keep_out)
{
    extern __shared__ unsigned char sraw[];
    u32* smaskT = (u32*)sraw;                  // 32*1024 words (transposed)
    u32* svalid = smaskT + 32 * 1024;          // 32
    u32* skeepv = svalid + 32;                 // 32
    int* schg   = (int*)(skeepv + 32);         // 2 (double-buffered flag)

    const int img  = blockIdx.x;
    const int tid  = threadIdx.x;
    const int warp = tid >> 5, lane = tid & 31;

    // fill transposed mask (128KB, coalesced, L2-resident)
    {
        const uint4* src = (const uint4*)(g_maskT + (size_t)img * 32 * 1024);
        uint4* dst = (uint4*)smaskT;
        #pragma unroll
        for (int r = 0; r < 8; r++)
            dst[tid + r * SWEEP_T] = src[tid + r * SWEEP_T];
    }

    // validity ballots; seed keep = valid
    {
        float sc = (tid < TOPK) ? g_score[img * 1024 + tid] : -1.0f;
        u32 vb = __ballot_sync(0xFFFFFFFFu, sc > CONF_T);
        if (lane == 0) { svalid[warp] = vb; skeepv[warp] = vb; }
        if (tid < 2) schg[tid] = 0;
    }
    __syncthreads();

    // Jacobi: keep <- valid & ~sup(keep); converges to greedy fixed point
    for (int it = 0; it < 1100; ++it) {
        int cur = it & 1;
        // warp w computes suppression word w; only chunks q <= w can hit it
        u32 partial = 0;
        for (int q = 0; q <= warp; q++) {
            u32 kw = skeepv[q];                       // broadcast
            u32 bm = 0u - ((kw >> lane) & 1u);        // lane owns row q*32+lane
            partial |= smaskT[warp * 1024 + q * 32 + lane] & bm;
        }
        u32 sup = __reduce_or_sync(0xFFFFFFFFu, partial);
        u32 nk  = svalid[warp] & ~sup;
        u32 old = skeepv[warp];
        __syncthreads();                              // readers done
        if (lane == 0) {
            skeepv[warp] = nk;
            if (nk != old) schg[cur] = 1;
        }
        if (tid == 0) schg[cur ^ 1] = 0;              // reset next flag
        __syncthreads();
        if (!schg[cur]) break;
    }

    // outputs
    const float* p = pred + (size_t)img * NPRED * PRED_C;
    if (tid < TOPK) {
        bool kp = (skeepv[tid >> 5] >> (tid & 31)) & 1u;
        float o0=0.f,o1=0.f,o2=0.f,o3=0.f,o4=0.f,o6=0.f,o7=0.f,o8=0.f;
        if (kp) {
            float4 b = g_box[img * 1024 + tid];
            o0 = b.x; o1 = b.y; o2 = b.z; o3 = b.w;
            o4 = g_score[img * 1024 + tid];
            int idx = g_idx[img * 1024 + tid];
            o6 = p[idx * PRED_C + 6];
            o7 = p[idx * PRED_C + 7];
            o8 = p[idx * PRED_C + 8];
        }
        float* orow = out + ((size_t)img * TOPK + tid) * PRED_C;
        orow[0]=o0; orow[1]=o1; orow[2]=o2; orow[3]=o3;
        orow[4]=o4; orow[5]=0.0f;
        orow[6]=o6; orow[7]=o7; orow[8]=o8;
        keep_out[(size_t)img * TOPK + tid] = kp ? 1.0f : 0.0f;
    }
}

extern "C" void kernel_launch(void* const* d_in, const int* in_sizes, int n_in,
                              void* d_out, int out_size)
{
    const float* pred = (const float*)d_in[0];
    int B = in_sizes[0] / (NPRED * PRED_C);

    float* out  = (float*)d_out;
    float* keep = out + (size_t)B * TOPK * PRED_C;

    size_t smemSort  = (size_t)CANDCAP * 8 + (size_t)SEL_N * 8 * 2 +
                       1024 * 4 + 64 * 4 + 80 * 4;
    size_t smemSweep = (size_t)32 * 1024 * 4 + 64 * 4 + 2 * 4 + 64;

    static bool attr_set = false;
    if (!attr_set) {
        cudaFuncSetAttribute(k_sort,  cudaFuncAttributeMaxDynamicSharedMemorySize,
                             (int)smemSort);
        cudaFuncSetAttribute(k_sweep, cudaFuncAttributeMaxDynamicSharedMemorySize,
                             (int)smemSweep);
        attr_set = true;
    }

    k_filter<<<dim3(B, NSLICE), FILT_T>>>(pred);
    k_sort<<<B, SORT_T, smemSort>>>(pred);
    k_mask<<<dim3(B, MSLICES), MASK_T>>>();
    k_sweep<<<B, SWEEP_T, smemSweep>>>(pred, out, keep);
}